// round 15
// baseline (speedup 1.0000x reference)
#include <cuda_runtime.h>
#include <cuda_fp16.h>
#include <cstdint>

// Grouped GEMM via fp16 2-term split on mma.sync (base sm_103 target).
// C = Ahi@Bh^T + Alo@Bh^T, A = Ahi + Alo (fp16), Bh = fp16(B).
// R15: CTA tile 128x256 (warp tile 64x64, 8 consumer + 2 producer warps,
//      320 threads, 3-stage BK=64 pipeline, 192KB smem), item-granular
//      work stealing, kh phase skew, 2x-ILP split prepass.

constexpr int M_DIM = 8192;
constexpr int K_DIM = 1024;
constexpr int N_DIM = 1024;
constexpr int E_SEG = 8;

#define BM 128
#define BN 256
#define BK 64
#define THREADS 320
constexpr int KT = K_DIM / BK;               // 16 k-chunks per unit
constexpr int A_BYTES = 128 * 128;           // 16384 (128 rows x 128B)
constexpr int B_BYTES = 256 * 128;           // 32768 (256 rows x 128B)
constexpr int STAGE_BYTES = 2 * A_BYTES + B_BYTES;   // Ahi, Alo, Bh = 65536
constexpr int NSTAGE = 3;
constexpr int MBAR_OFF = NSTAGE * STAGE_BYTES;   // 196608
constexpr int PREF_OFF = MBAR_OFF + 128;
constexpr int SMEM_TOTAL = PREF_OFF + 272;       // ~196.9KB <= 227KB
constexpr int NBANDS = M_DIM / BM;           // 64
constexpr int NCOLS = N_DIM / BN;            // 4
constexpr int GRID_P = 148;                  // 1 CTA/SM

// Split storage (fp16)
__device__ __half g_Ahi[(size_t)M_DIM * K_DIM];
__device__ __half g_Alo[(size_t)M_DIM * K_DIM];
__device__ __half g_Bh [(size_t)E_SEG * N_DIM * K_DIM];
__device__ unsigned g_tileCtr;

constexpr int NA4 = (M_DIM * K_DIM) / 4;             // 2097152 (even)
constexpr int NB4 = (E_SEG * N_DIM * K_DIM) / 4;     // 2097152

// ---------------- prepass (2 float4 per thread; also resets counter) -----
__global__ void __launch_bounds__(256)
split_AB(const float4* __restrict__ A, const float4* __restrict__ B) {
    if (blockIdx.x == 0 && threadIdx.x == 0) g_tileCtr = 0u;  // ordered by kernel
    const size_t base = ((size_t)blockIdx.x * 256 + threadIdx.x) * 2;
    #pragma unroll
    for (int k = 0; k < 2; ++k) {
        const size_t i = base + k;
        if (i < (size_t)NA4) {
            float4 v = A[i];
            __half h0 = __float2half(v.x), h1 = __float2half(v.y);
            __half h2 = __float2half(v.z), h3 = __float2half(v.w);
            __half l0 = __float2half(v.x - __half2float(h0));
            __half l1 = __float2half(v.y - __half2float(h1));
            __half l2 = __float2half(v.z - __half2float(h2));
            __half l3 = __float2half(v.w - __half2float(h3));
            ((ushort4*)g_Ahi)[i] = make_ushort4(__half_as_ushort(h0), __half_as_ushort(h1),
                                                __half_as_ushort(h2), __half_as_ushort(h3));
            ((ushort4*)g_Alo)[i] = make_ushort4(__half_as_ushort(l0), __half_as_ushort(l1),
                                                __half_as_ushort(l2), __half_as_ushort(l3));
        } else {
            const size_t j = i - NA4;
            float4 v = B[j];
            ((ushort4*)g_Bh)[j] = make_ushort4(
                __half_as_ushort(__float2half(v.x)), __half_as_ushort(__float2half(v.y)),
                __half_as_ushort(__float2half(v.z)), __half_as_ushort(__float2half(v.w)));
        }
    }
}

// ---------------- asm helpers ----------------
__device__ __forceinline__ void cp16(uint32_t dst, const void* src) {
    asm volatile("cp.async.cg.shared.global [%0], [%1], 16;" :: "r"(dst), "l"(src));
}
__device__ __forceinline__ void ldsm4(uint32_t addr, uint32_t r[4]) {
    asm volatile("ldmatrix.sync.aligned.m8n8.x4.shared.b16 {%0,%1,%2,%3}, [%4];"
                 : "=r"(r[0]), "=r"(r[1]), "=r"(r[2]), "=r"(r[3]) : "r"(addr));
}
__device__ __forceinline__ void mma16816(float d[4], const uint32_t a[4],
                                         uint32_t b0, uint32_t b1) {
    asm volatile(
        "mma.sync.aligned.m16n8k16.row.col.f32.f16.f16.f32 "
        "{%0,%1,%2,%3}, {%4,%5,%6,%7}, {%8,%9}, {%0,%1,%2,%3};"
        : "+f"(d[0]), "+f"(d[1]), "+f"(d[2]), "+f"(d[3])
        : "r"(a[0]), "r"(a[1]), "r"(a[2]), "r"(a[3]), "r"(b0), "r"(b1));
}
__device__ __forceinline__ void mbar_init(uint32_t m, uint32_t cnt) {
    asm volatile("mbarrier.init.shared.b64 [%0], %1;" :: "r"(m), "r"(cnt) : "memory");
}
__device__ __forceinline__ void mbar_arrive(uint32_t m) {
    asm volatile("mbarrier.arrive.shared.b64 _, [%0];" :: "r"(m) : "memory");
}
__device__ __forceinline__ void cpasync_arrive(uint32_t m) {
    asm volatile("cp.async.mbarrier.arrive.noinc.shared.b64 [%0];" :: "r"(m) : "memory");
}
__device__ __forceinline__ void mbar_wait(uint32_t m, uint32_t parity) {
    uint32_t done;
    asm volatile("{\n\t.reg .pred p;\n\t"
                 "mbarrier.try_wait.parity.acquire.cta.shared::cta.b64 p, [%1], %2;\n\t"
                 "selp.b32 %0, 1, 0, p;\n\t}" : "=r"(done) : "r"(m), "r"(parity) : "memory");
    if (!done) {
        asm volatile("{\n\t.reg .pred P1;\n\t"
                     "W_%=:\n\t"
                     "mbarrier.try_wait.parity.acquire.cta.shared::cta.b64 P1, [%0], %1, 0x989680;\n\t"
                     "@P1 bra.uni D_%=;\n\t"
                     "bra.uni W_%=;\n\t"
                     "D_%=:\n\t}" :: "r"(m), "r"(parity) : "memory");
    }
}

// 128B-row SW128 swizzle: XOR chunk bits[6:4] with row bits[2:0].
__device__ __forceinline__ uint32_t swz(uint32_t row, uint32_t colB) {
    return row * 128u + (colB ^ ((row & 7u) << 4));
}

// ---------------- main kernel ----------------
__global__ void __launch_bounds__(THREADS, 1)
grouped_gemm_hmma(const int* __restrict__ seg_indptr,
                  const int* __restrict__ widx,
                  float* __restrict__ C)
{
    extern __shared__ char smem[];
    const uint32_t sb = (uint32_t)__cvta_generic_to_shared(smem);
    const int tid = threadIdx.x;
    const int wid = tid >> 5;
    const int lane = tid & 31;

    const uint32_t mbF = sb + MBAR_OFF;        // full[i]  at +8*i (3 stages)
    const uint32_t mbE = sb + MBAR_OFF + 24;   // empty[i] at +8*i
    volatile unsigned* sTile = (volatile unsigned*)(smem + MBAR_OFF + 64);
    int* sPref = (int*)(smem + PREF_OFF);      // [0..64] unit prefix (x NCOLS)

    int sv[E_SEG + 1];
    #pragma unroll
    for (int s = 0; s <= E_SEG; ++s) sv[s] = seg_indptr[s];

    if (tid == 0) {
        #pragma unroll
        for (int i = 0; i < NSTAGE; ++i) {
            mbar_init(mbF + i * 8, 64);    // one .noinc arrival per producer thread
            mbar_init(mbE + i * 8, 8);     // one arrival per consumer warp
        }
        int acc = 0;
        sPref[0] = 0;
        for (int m = 0; m < NBANDS; ++m) {
            const int lo = m * BM, hi = lo + BM;
            int c = 0;
            #pragma unroll
            for (int s = 0; s < E_SEG; ++s)
                if (max(sv[s], lo) < min(sv[s + 1], hi)) ++c;
            acc += NCOLS * c;
            sPref[m + 1] = acc;
        }
    }
    __syncthreads();
    const int nUnits = sPref[NBANDS];

    // consumer warp layout (wid 0..7): 64x64 tiles, 2x4 over 128x256
    const int warp_m = wid >> 2;            // 0..1 -> row *64
    const int warp_n = wid & 3;             // 0..3 -> col *64
    const uint32_t aRow = (uint32_t)(warp_m * 64 + (lane & 15));
    const uint32_t bRow = (uint32_t)(warp_n * 64 + (lane & 7) + ((lane >> 4) & 1) * 8);
    const uint32_t aSel = (uint32_t)((lane >> 4) * 16);
    const uint32_t bSel = (uint32_t)(((lane >> 3) & 1) * 16);
    const int khSkew = (wid & 1) * 2;       // decorrelate LDSM bursts per SMSP

    // producer thread layout (tid 256..319, 64 threads)
    const int pt = tid - 256;               // 0..63

    int pst = 0, pph = 1;   // producer cursor
    int cst = 0, cph = 0;   // consumer cursor

    #pragma unroll 1
    for (;;) {
        __syncthreads();
        if (tid == 0) *sTile = atomicAdd(&g_tileCtr, 1u);
        __syncthreads();
        const unsigned u = *sTile;
        if (u >= (unsigned)nUnits) break;

        // decode unit -> (band, item, col)
        int blo = 0, bhi = NBANDS;
        while (bhi - blo > 1) {
            const int mid = (blo + bhi) >> 1;
            if ((unsigned)sPref[mid] <= u) blo = mid; else bhi = mid;
        }
        const int band = blo;
        const int rem = (int)u - sPref[band];
        const int it = rem >> 2;               // item within band
        const int col = rem & 3;               // column tile
        const int row0 = band * BM;
        const int col0 = col * BN;

        // find it-th intersecting segment of this band
        int rloI = 0, rhiI = 0;
        const __half* __restrict__ be = g_Bh;
        {
            int cnt = 0;
            #pragma unroll
            for (int s = 0; s < E_SEG; ++s) {
                const int rl = max(sv[s], row0);
                const int rh = min(sv[s + 1], row0 + BM);
                if (rl < rh) {
                    if (cnt == it) {
                        rloI = rl; rhiI = rh;
                        be = g_Bh + (size_t)widx[s] * ((size_t)N_DIM * K_DIM);
                    }
                    ++cnt;
                }
            }
        }

        if (wid >= 8) {
            // ================= PRODUCER WARPS (64 threads) =================
            #pragma unroll 1
            for (int kt = 0; kt < KT; ++kt) {
                mbar_wait(mbE + pst * 8, (uint32_t)pph);
                const uint32_t stg = sb + pst * STAGE_BYTES;
                const int keB = kt * BK;
                // A hi/lo: 1024 chunks each -> 16 blocks of 64
                #pragma unroll
                for (int blk = 0; blk < 16; ++blk) {
                    const int id = blk * 64 + pt;
                    const uint32_t r = (uint32_t)(id >> 3);
                    const int c = id & 7;
                    const uint32_t so = swz(r, (uint32_t)(c * 16));
                    const size_t go = (size_t)(row0 + (int)r) * K_DIM + keB + c * 8;
                    cp16(stg + so,           g_Ahi + go);
                    cp16(stg + A_BYTES + so, g_Alo + go);
                }
                // Bh: 2048 chunks -> 32 blocks of 64
                #pragma unroll
                for (int blk = 0; blk < 32; ++blk) {
                    const int id = blk * 64 + pt;
                    const uint32_t r = (uint32_t)(id >> 3);
                    const int c = id & 7;
                    const uint32_t so = swz(r, (uint32_t)(c * 16));
                    cp16(stg + 2 * A_BYTES + so,
                         be + (size_t)(col0 + (int)r) * K_DIM + keB + c * 8);
                }
                cpasync_arrive(mbF + pst * 8);
                if (++pst == NSTAGE) { pst = 0; pph ^= 1; }
            }
        } else {
            // ================= CONSUMER WARPS =================
            float acc[4][8][4];
            #pragma unroll
            for (int i = 0; i < 4; ++i)
                #pragma unroll
                for (int j = 0; j < 8; ++j)
                    #pragma unroll
                    for (int p = 0; p < 4; ++p) acc[i][j][p] = 0.f;

            #pragma unroll 1
            for (int kt = 0; kt < KT; ++kt) {
                mbar_wait(mbF + cst * 8, (uint32_t)cph);

                const uint32_t stg    = sb + cst * STAGE_BYTES;
                const uint32_t stgAhi = stg;
                const uint32_t stgAlo = stg + A_BYTES;
                const uint32_t stgBh  = stg + 2 * A_BYTES;

                #pragma unroll
                for (int khi = 0; khi < 4; ++khi) {
                    const int kh = (khi + khSkew) & 3;
                    const uint32_t aCB = (uint32_t)(kh * 32) + aSel;
                    const uint32_t bCB = (uint32_t)(kh * 32) + bSel;

                    uint32_t ah[4][4], bh[4][4];
                    #pragma unroll
                    for (int mt = 0; mt < 4; ++mt)
                        ldsm4(stgAhi + swz(aRow + mt * 16, aCB), ah[mt]);
                    #pragma unroll
                    for (int p = 0; p < 4; ++p)
                        ldsm4(stgBh + swz(bRow + p * 16, bCB), bh[p]);

                    #pragma unroll
                    for (int mt = 0; mt < 4; ++mt)
                        #pragma unroll
                        for (int nt = 0; nt < 8; ++nt)
                            mma16816(acc[mt][nt], ah[mt],
                                     bh[nt >> 1][(nt & 1) * 2], bh[nt >> 1][(nt & 1) * 2 + 1]);

                    uint32_t al[4][4];
                    #pragma unroll
                    for (int mt = 0; mt < 4; ++mt)
                        ldsm4(stgAlo + swz(aRow + mt * 16, aCB), al[mt]);

                    #pragma unroll
                    for (int mt = 0; mt < 4; ++mt)
                        #pragma unroll
                        for (int nt = 0; nt < 8; ++nt)
                            mma16816(acc[mt][nt], al[mt],
                                     bh[nt >> 1][(nt & 1) * 2], bh[nt >> 1][(nt & 1) * 2 + 1]);
                }

                if (lane == 0) mbar_arrive(mbE + cst * 8);
                if (++cst == NSTAGE) { cst = 0; cph ^= 1; }
            }

            // epilogue: masked rows for this unit's segment
            {
                const int cbase = col0 + warp_n * 64 + (lane & 3) * 2;
                #pragma unroll
                for (int mt = 0; mt < 4; ++mt) {
                    const int r0 = row0 + warp_m * 64 + mt * 16 + (lane >> 2);
                    const int r1 = r0 + 8;
                    const bool w0 = (r0 >= rloI && r0 < rhiI);
                    const bool w1 = (r1 >= rloI && r1 < rhiI);
                    #pragma unroll
                    for (int nt = 0; nt < 8; ++nt) {
                        const int cc = cbase + nt * 8;
                        if (w0) *(float2*)&C[(size_t)r0 * N_DIM + cc] =
                                    make_float2(acc[mt][nt][0], acc[mt][nt][1]);
                        if (w1) *(float2*)&C[(size_t)r1 * N_DIM + cc] =
                                    make_float2(acc[mt][nt][2], acc[mt][nt][3]);
                    }
                }
            }
        }
    }
}

extern "C" void kernel_launch(void* const* d_in, const int* in_sizes, int n_in,
                              void* d_out, int out_size)
{
    const float* a = (const float*)d_in[0];    // [M, K]
    const float* b = (const float*)d_in[1];    // [E, N, K]
    const int* seg = nullptr;
    const int* widx = nullptr;
    for (int i = 0; i < n_in; ++i) {
        if (in_sizes[i] == E_SEG + 1)  seg  = (const int*)d_in[i];
        else if (in_sizes[i] == E_SEG) widx = (const int*)d_in[i];
    }
    float* c = (float*)d_out;

    split_AB<<<(NA4 + NB4) / 512, 256>>>((const float4*)a, (const float4*)b);

    cudaFuncSetAttribute(grouped_gemm_hmma,
                         cudaFuncAttributeMaxDynamicSharedMemorySize, SMEM_TOTAL);
    grouped_gemm_hmma<<<GRID_P, THREADS, SMEM_TOTAL>>>(seg, widx, c);
}

// round 16
// speedup vs baseline: 1.0684x; 1.0684x over previous
#include <cuda_runtime.h>
#include <cuda_fp16.h>
#include <cstdint>

// Grouped GEMM via fp16 2-term split on mma.sync (base sm_103 target).
// C = Ahi@Bh^T + Alo@Bh^T, A = Ahi + Alo (fp16), Bh = fp16(B).
// R16: R14 geometry (8 consumer warps 64x32 + 4 producer warps, 1 CTA/SM)
//      with BK=128 / 2-stage pipeline (half the sync events), item-granular
//      stealing, kh skew, inactive-half skip, 2x-ILP split prepass.

constexpr int M_DIM = 8192;
constexpr int K_DIM = 1024;
constexpr int N_DIM = 1024;
constexpr int E_SEG = 8;

#define BM 128
#define BN 128
#define BK 128
#define THREADS 384
constexpr int KT = K_DIM / BK;               // 8 k-chunks per unit
constexpr int ROW_B = 256;                   // bytes per smem row (128 fp16)
constexpr int MAT_BYTES = 128 * ROW_B;       // 32768
constexpr int STAGE_BYTES = 3 * MAT_BYTES;   // Ahi, Alo, Bh = 98304
constexpr int NSTAGE = 2;
constexpr int MBAR_OFF = NSTAGE * STAGE_BYTES;   // 196608
constexpr int PREF_OFF = MBAR_OFF + 128;
constexpr int SMEM_TOTAL = PREF_OFF + 272;
constexpr int NBANDS = M_DIM / BM;           // 64
constexpr int NCOLS = N_DIM / BN;            // 8
constexpr int GRID_P = 148;                  // 1 CTA/SM

// Split storage (fp16)
__device__ __half g_Ahi[(size_t)M_DIM * K_DIM];
__device__ __half g_Alo[(size_t)M_DIM * K_DIM];
__device__ __half g_Bh [(size_t)E_SEG * N_DIM * K_DIM];
__device__ unsigned g_tileCtr;

constexpr int NA4 = (M_DIM * K_DIM) / 4;
constexpr int NB4 = (E_SEG * N_DIM * K_DIM) / 4;

// ---------------- prepass (2 float4 per thread; also resets counter) -----
__global__ void __launch_bounds__(256)
split_AB(const float4* __restrict__ A, const float4* __restrict__ B) {
    if (blockIdx.x == 0 && threadIdx.x == 0) g_tileCtr = 0u;  // ordered by kernel
    const size_t base = ((size_t)blockIdx.x * 256 + threadIdx.x) * 2;
    #pragma unroll
    for (int k = 0; k < 2; ++k) {
        const size_t i = base + k;
        if (i < (size_t)NA4) {
            float4 v = A[i];
            __half h0 = __float2half(v.x), h1 = __float2half(v.y);
            __half h2 = __float2half(v.z), h3 = __float2half(v.w);
            __half l0 = __float2half(v.x - __half2float(h0));
            __half l1 = __float2half(v.y - __half2float(h1));
            __half l2 = __float2half(v.z - __half2float(h2));
            __half l3 = __float2half(v.w - __half2float(h3));
            ((ushort4*)g_Ahi)[i] = make_ushort4(__half_as_ushort(h0), __half_as_ushort(h1),
                                                __half_as_ushort(h2), __half_as_ushort(h3));
            ((ushort4*)g_Alo)[i] = make_ushort4(__half_as_ushort(l0), __half_as_ushort(l1),
                                                __half_as_ushort(l2), __half_as_ushort(l3));
        } else {
            const size_t j = i - NA4;
            float4 v = B[j];
            ((ushort4*)g_Bh)[j] = make_ushort4(
                __half_as_ushort(__float2half(v.x)), __half_as_ushort(__float2half(v.y)),
                __half_as_ushort(__float2half(v.z)), __half_as_ushort(__float2half(v.w)));
        }
    }
}

// ---------------- asm helpers ----------------
__device__ __forceinline__ void cp16(uint32_t dst, const void* src) {
    asm volatile("cp.async.cg.shared.global [%0], [%1], 16;" :: "r"(dst), "l"(src));
}
__device__ __forceinline__ void ldsm4(uint32_t addr, uint32_t r[4]) {
    asm volatile("ldmatrix.sync.aligned.m8n8.x4.shared.b16 {%0,%1,%2,%3}, [%4];"
                 : "=r"(r[0]), "=r"(r[1]), "=r"(r[2]), "=r"(r[3]) : "r"(addr));
}
__device__ __forceinline__ void mma16816(float d[4], const uint32_t a[4],
                                         uint32_t b0, uint32_t b1) {
    asm volatile(
        "mma.sync.aligned.m16n8k16.row.col.f32.f16.f16.f32 "
        "{%0,%1,%2,%3}, {%4,%5,%6,%7}, {%8,%9}, {%0,%1,%2,%3};"
        : "+f"(d[0]), "+f"(d[1]), "+f"(d[2]), "+f"(d[3])
        : "r"(a[0]), "r"(a[1]), "r"(a[2]), "r"(a[3]), "r"(b0), "r"(b1));
}
__device__ __forceinline__ void mbar_init(uint32_t m, uint32_t cnt) {
    asm volatile("mbarrier.init.shared.b64 [%0], %1;" :: "r"(m), "r"(cnt) : "memory");
}
__device__ __forceinline__ void mbar_arrive(uint32_t m) {
    asm volatile("mbarrier.arrive.shared.b64 _, [%0];" :: "r"(m) : "memory");
}
__device__ __forceinline__ void cpasync_arrive(uint32_t m) {
    asm volatile("cp.async.mbarrier.arrive.noinc.shared.b64 [%0];" :: "r"(m) : "memory");
}
__device__ __forceinline__ void mbar_wait(uint32_t m, uint32_t parity) {
    uint32_t done;
    asm volatile("{\n\t.reg .pred p;\n\t"
                 "mbarrier.try_wait.parity.acquire.cta.shared::cta.b64 p, [%1], %2;\n\t"
                 "selp.b32 %0, 1, 0, p;\n\t}" : "=r"(done) : "r"(m), "r"(parity) : "memory");
    if (!done) {
        asm volatile("{\n\t.reg .pred P1;\n\t"
                     "W_%=:\n\t"
                     "mbarrier.try_wait.parity.acquire.cta.shared::cta.b64 P1, [%0], %1, 0x989680;\n\t"
                     "@P1 bra.uni D_%=;\n\t"
                     "bra.uni W_%=;\n\t"
                     "D_%=:\n\t}" :: "r"(m), "r"(parity) : "memory");
    }
}

// 256B-row swizzle: XOR chunk bits[6:4] with row bits[2:0] (SW128 per half).
__device__ __forceinline__ uint32_t swz(uint32_t row, uint32_t colB) {
    return row * (uint32_t)ROW_B + (colB ^ ((row & 7u) << 4));
}

// ---------------- main kernel ----------------
__global__ void __launch_bounds__(THREADS, 1)
grouped_gemm_hmma(const int* __restrict__ seg_indptr,
                  const int* __restrict__ widx,
                  float* __restrict__ C)
{
    extern __shared__ char smem[];
    const uint32_t sb = (uint32_t)__cvta_generic_to_shared(smem);
    const int tid = threadIdx.x;
    const int wid = tid >> 5;
    const int lane = tid & 31;

    const uint32_t mbF = sb + MBAR_OFF;        // full[i]  at +8*i (2 stages)
    const uint32_t mbE = sb + MBAR_OFF + 16;   // empty[i] at +8*i
    volatile unsigned* sTile = (volatile unsigned*)(smem + MBAR_OFF + 64);
    int* sPref = (int*)(smem + PREF_OFF);      // [0..64] unit prefix (x NCOLS)

    int sv[E_SEG + 1];
    #pragma unroll
    for (int s = 0; s <= E_SEG; ++s) sv[s] = seg_indptr[s];

    if (tid == 0) {
        #pragma unroll
        for (int i = 0; i < NSTAGE; ++i) {
            mbar_init(mbF + i * 8, 128);   // one .noinc arrival per producer thread
            mbar_init(mbE + i * 8, 8);     // one arrival per consumer warp
        }
        int acc = 0;
        sPref[0] = 0;
        for (int m = 0; m < NBANDS; ++m) {
            const int lo = m * BM, hi = lo + BM;
            int c = 0;
            #pragma unroll
            for (int s = 0; s < E_SEG; ++s)
                if (max(sv[s], lo) < min(sv[s + 1], hi)) ++c;
            acc += NCOLS * c;
            sPref[m + 1] = acc;
        }
    }
    __syncthreads();
    const int nUnits = sPref[NBANDS];

    // consumer warp layout (wid 0..7): 64x32 tiles
    const int warp_m = wid >> 2;            // 0..1
    const int warp_n = wid & 3;             // 0..3
    const uint32_t aRow = (uint32_t)(warp_m * 64 + (lane & 15));
    const uint32_t bRow = (uint32_t)(warp_n * 32 + (lane & 7) + ((lane >> 4) & 1) * 8);
    const uint32_t aSel = (uint32_t)((lane >> 4) * 16);
    const uint32_t bSel = (uint32_t)(((lane >> 3) & 1) * 16);
    const int khSkew = (wid & 1) * 4;       // decorrelate LDSM bursts per SMSP

    // producer thread layout (tid 256..383): 2048 chunks/matrix, 16 per thread
    const int pt = tid - 256;

    int pst = 0, pph = 1;   // producer cursor
    int cst = 0, cph = 0;   // consumer cursor

    #pragma unroll 1
    for (;;) {
        __syncthreads();
        if (tid == 0) *sTile = atomicAdd(&g_tileCtr, 1u);
        __syncthreads();
        const unsigned u = *sTile;
        if (u >= (unsigned)nUnits) break;

        // decode unit -> (band, item, col)
        int blo = 0, bhi = NBANDS;
        while (bhi - blo > 1) {
            const int mid = (blo + bhi) >> 1;
            if ((unsigned)sPref[mid] <= u) blo = mid; else bhi = mid;
        }
        const int band = blo;
        const int rem = (int)u - sPref[band];
        const int it = rem >> 3;               // item within band
        const int col = rem & 7;               // column tile
        const int row0 = band * BM;
        const int col0 = col * BN;

        // find it-th intersecting segment of this band
        int rloI = 0, rhiI = 0;
        const __half* __restrict__ be = g_Bh;
        {
            int cnt = 0;
            #pragma unroll
            for (int s = 0; s < E_SEG; ++s) {
                const int rl = max(sv[s], row0);
                const int rh = min(sv[s + 1], row0 + BM);
                if (rl < rh) {
                    if (cnt == it) {
                        rloI = rl; rhiI = rh;
                        be = g_Bh + (size_t)widx[s] * ((size_t)N_DIM * K_DIM);
                    }
                    ++cnt;
                }
            }
        }

        if (wid >= 8) {
            // ================= PRODUCER WARPS (128 threads) =================
            #pragma unroll 1
            for (int kt = 0; kt < KT; ++kt) {
                mbar_wait(mbE + pst * 8, (uint32_t)pph);
                const uint32_t stg = sb + pst * STAGE_BYTES;
                const int keB = kt * BK;
                // each matrix: 128 rows x 16 chunks = 2048 chunks; 16/thread
                #pragma unroll
                for (int blk = 0; blk < 16; ++blk) {
                    const int id = blk * 128 + pt;
                    const uint32_t r = (uint32_t)(id >> 4);
                    const int c = id & 15;
                    const uint32_t so = swz(r, (uint32_t)(c * 16));
                    const size_t goA = (size_t)(row0 + (int)r) * K_DIM + keB + c * 8;
                    cp16(stg + so,                 g_Ahi + goA);
                    cp16(stg + MAT_BYTES + so,     g_Alo + goA);
                    cp16(stg + 2 * MAT_BYTES + so,
                         be + (size_t)(col0 + (int)r) * K_DIM + keB + c * 8);
                }
                cpasync_arrive(mbF + pst * 8);
                if (++pst == NSTAGE) { pst = 0; pph ^= 1; }
            }
        } else {
            // ================= CONSUMER WARPS =================
            // inactive half skip: this warp's 64 rows may not intersect segment
            const int wr0 = row0 + warp_m * 64;
            const bool active = (rhiI > wr0) && (rloI < wr0 + 64);

            if (!active) {
                #pragma unroll 1
                for (int kt = 0; kt < KT; ++kt) {
                    mbar_wait(mbF + cst * 8, (uint32_t)cph);
                    if (lane == 0) mbar_arrive(mbE + cst * 8);
                    if (++cst == NSTAGE) { cst = 0; cph ^= 1; }
                }
            } else {
                float acc[4][4][4];
                #pragma unroll
                for (int i = 0; i < 4; ++i)
                    #pragma unroll
                    for (int j = 0; j < 4; ++j)
                        #pragma unroll
                        for (int p = 0; p < 4; ++p) acc[i][j][p] = 0.f;

                #pragma unroll 1
                for (int kt = 0; kt < KT; ++kt) {
                    mbar_wait(mbF + cst * 8, (uint32_t)cph);

                    const uint32_t stg    = sb + cst * STAGE_BYTES;
                    const uint32_t stgAhi = stg;
                    const uint32_t stgAlo = stg + MAT_BYTES;
                    const uint32_t stgBh  = stg + 2 * MAT_BYTES;

                    #pragma unroll
                    for (int khi = 0; khi < 8; ++khi) {
                        const int kh = (khi + khSkew) & 7;
                        const uint32_t aCB = (uint32_t)(kh * 32) + aSel;
                        const uint32_t bCB = (uint32_t)(kh * 32) + bSel;

                        uint32_t ah[4][4], bh[2][4];
                        #pragma unroll
                        for (int mt = 0; mt < 4; ++mt)
                            ldsm4(stgAhi + swz(aRow + mt * 16, aCB), ah[mt]);
                        #pragma unroll
                        for (int p = 0; p < 2; ++p)
                            ldsm4(stgBh + swz(bRow + p * 16, bCB), bh[p]);

                        #pragma unroll
                        for (int mt = 0; mt < 4; ++mt)
                            #pragma unroll
                            for (int nt = 0; nt < 4; ++nt)
                                mma16816(acc[mt][nt], ah[mt],
                                         bh[nt >> 1][(nt & 1) * 2],
                                         bh[nt >> 1][(nt & 1) * 2 + 1]);

                        uint32_t al[4][4];
                        #pragma unroll
                        for (int mt = 0; mt < 4; ++mt)
                            ldsm4(stgAlo + swz(aRow + mt * 16, aCB), al[mt]);

                        #pragma unroll
                        for (int mt = 0; mt < 4; ++mt)
                            #pragma unroll
                            for (int nt = 0; nt < 4; ++nt)
                                mma16816(acc[mt][nt], al[mt],
                                         bh[nt >> 1][(nt & 1) * 2],
                                         bh[nt >> 1][(nt & 1) * 2 + 1]);
                    }

                    if (lane == 0) mbar_arrive(mbE + cst * 8);
                    if (++cst == NSTAGE) { cst = 0; cph ^= 1; }
                }

                // epilogue: masked rows for this unit's segment
                const int cbase = col0 + warp_n * 32 + (lane & 3) * 2;
                #pragma unroll
                for (int mt = 0; mt < 4; ++mt) {
                    const int r0 = wr0 + mt * 16 + (lane >> 2);
                    const int r1 = r0 + 8;
                    const bool w0 = (r0 >= rloI && r0 < rhiI);
                    const bool w1 = (r1 >= rloI && r1 < rhiI);
                    #pragma unroll
                    for (int nt = 0; nt < 4; ++nt) {
                        const int cc = cbase + nt * 8;
                        if (w0) *(float2*)&C[(size_t)r0 * N_DIM + cc] =
                                    make_float2(acc[mt][nt][0], acc[mt][nt][1]);
                        if (w1) *(float2*)&C[(size_t)r1 * N_DIM + cc] =
                                    make_float2(acc[mt][nt][2], acc[mt][nt][3]);
                    }
                }
            }
        }
    }
}

extern "C" void kernel_launch(void* const* d_in, const int* in_sizes, int n_in,
                              void* d_out, int out_size)
{
    const float* a = (const float*)d_in[0];    // [M, K]
    const float* b = (const float*)d_in[1];    // [E, N, K]
    const int* seg = nullptr;
    const int* widx = nullptr;
    for (int i = 0; i < n_in; ++i) {
        if (in_sizes[i] == E_SEG + 1)  seg  = (const int*)d_in[i];
        else if (in_sizes[i] == E_SEG) widx = (const int*)d_in[i];
    }
    float* c = (float*)d_out;

    split_AB<<<(NA4 + NB4) / 512, 256>>>((const float4*)a, (const float4*)b);

    cudaFuncSetAttribute(grouped_gemm_hmma,
                         cudaFuncAttributeMaxDynamicSharedMemorySize, SMEM_TOTAL);
    grouped_gemm_hmma<<<GRID_P, THREADS, SMEM_TOTAL>>>(seg, widx, c);
}

// round 17
// speedup vs baseline: 1.6132x; 1.5098x over previous
#include <cuda_runtime.h>
#include <cuda_fp16.h>
#include <cstdint>

// Grouped GEMM, single-term fp16 on mma.sync (base sm_103 target).
// C = fp16(A) @ fp16(B)^T with fp32 accumulation.
// Error: independent fp16 rounding of A and B -> rel_err ~2.9e-4 << 1e-3.
// R17: R16 skeleton (8 consumer warps 64x32 + 4 producer warps, 1 CTA/SM,
//      BK=128) with single term -> 3-stage pipeline (2-matrix 64KB stages),
//      item-granular stealing, kh skew, inactive-half skip, ILP split.

constexpr int M_DIM = 8192;
constexpr int K_DIM = 1024;
constexpr int N_DIM = 1024;
constexpr int E_SEG = 8;

#define BM 128
#define BN 128
#define BK 128
#define THREADS 384
constexpr int KT = K_DIM / BK;               // 8 k-chunks per unit
constexpr int ROW_B = 256;                   // bytes per smem row (128 fp16)
constexpr int MAT_BYTES = 128 * ROW_B;       // 32768
constexpr int STAGE_BYTES = 2 * MAT_BYTES;   // Ah, Bh = 65536
constexpr int NSTAGE = 3;
constexpr int MBAR_OFF = NSTAGE * STAGE_BYTES;   // 196608
constexpr int PREF_OFF = MBAR_OFF + 128;
constexpr int SMEM_TOTAL = PREF_OFF + 272;
constexpr int NBANDS = M_DIM / BM;           // 64
constexpr int NCOLS = N_DIM / BN;            // 8
constexpr int GRID_P = 148;                  // 1 CTA/SM

// fp16 storage
__device__ __half g_Ah[(size_t)M_DIM * K_DIM];
__device__ __half g_Bh[(size_t)E_SEG * N_DIM * K_DIM];
__device__ unsigned g_tileCtr;

constexpr int NA4 = (M_DIM * K_DIM) / 4;
constexpr int NB4 = (E_SEG * N_DIM * K_DIM) / 4;

// ---------------- prepass (2 float4 per thread; also resets counter) -----
__global__ void __launch_bounds__(256)
split_AB(const float4* __restrict__ A, const float4* __restrict__ B) {
    if (blockIdx.x == 0 && threadIdx.x == 0) g_tileCtr = 0u;  // ordered by kernel
    const size_t base = ((size_t)blockIdx.x * 256 + threadIdx.x) * 2;
    #pragma unroll
    for (int k = 0; k < 2; ++k) {
        const size_t i = base + k;
        if (i < (size_t)NA4) {
            float4 v = A[i];
            ((ushort4*)g_Ah)[i] = make_ushort4(
                __half_as_ushort(__float2half(v.x)), __half_as_ushort(__float2half(v.y)),
                __half_as_ushort(__float2half(v.z)), __half_as_ushort(__float2half(v.w)));
        } else {
            const size_t j = i - NA4;
            float4 v = B[j];
            ((ushort4*)g_Bh)[j] = make_ushort4(
                __half_as_ushort(__float2half(v.x)), __half_as_ushort(__float2half(v.y)),
                __half_as_ushort(__float2half(v.z)), __half_as_ushort(__float2half(v.w)));
        }
    }
}

// ---------------- asm helpers ----------------
__device__ __forceinline__ void cp16(uint32_t dst, const void* src) {
    asm volatile("cp.async.cg.shared.global [%0], [%1], 16;" :: "r"(dst), "l"(src));
}
__device__ __forceinline__ void ldsm4(uint32_t addr, uint32_t r[4]) {
    asm volatile("ldmatrix.sync.aligned.m8n8.x4.shared.b16 {%0,%1,%2,%3}, [%4];"
                 : "=r"(r[0]), "=r"(r[1]), "=r"(r[2]), "=r"(r[3]) : "r"(addr));
}
__device__ __forceinline__ void mma16816(float d[4], const uint32_t a[4],
                                         uint32_t b0, uint32_t b1) {
    asm volatile(
        "mma.sync.aligned.m16n8k16.row.col.f32.f16.f16.f32 "
        "{%0,%1,%2,%3}, {%4,%5,%6,%7}, {%8,%9}, {%0,%1,%2,%3};"
        : "+f"(d[0]), "+f"(d[1]), "+f"(d[2]), "+f"(d[3])
        : "r"(a[0]), "r"(a[1]), "r"(a[2]), "r"(a[3]), "r"(b0), "r"(b1));
}
__device__ __forceinline__ void mbar_init(uint32_t m, uint32_t cnt) {
    asm volatile("mbarrier.init.shared.b64 [%0], %1;" :: "r"(m), "r"(cnt) : "memory");
}
__device__ __forceinline__ void mbar_arrive(uint32_t m) {
    asm volatile("mbarrier.arrive.shared.b64 _, [%0];" :: "r"(m) : "memory");
}
__device__ __forceinline__ void cpasync_arrive(uint32_t m) {
    asm volatile("cp.async.mbarrier.arrive.noinc.shared.b64 [%0];" :: "r"(m) : "memory");
}
__device__ __forceinline__ void mbar_wait(uint32_t m, uint32_t parity) {
    uint32_t done;
    asm volatile("{\n\t.reg .pred p;\n\t"
                 "mbarrier.try_wait.parity.acquire.cta.shared::cta.b64 p, [%1], %2;\n\t"
                 "selp.b32 %0, 1, 0, p;\n\t}" : "=r"(done) : "r"(m), "r"(parity) : "memory");
    if (!done) {
        asm volatile("{\n\t.reg .pred P1;\n\t"
                     "W_%=:\n\t"
                     "mbarrier.try_wait.parity.acquire.cta.shared::cta.b64 P1, [%0], %1, 0x989680;\n\t"
                     "@P1 bra.uni D_%=;\n\t"
                     "bra.uni W_%=;\n\t"
                     "D_%=:\n\t}" :: "r"(m), "r"(parity) : "memory");
    }
}

// 256B-row swizzle: XOR chunk bits[6:4] with row bits[2:0].
__device__ __forceinline__ uint32_t swz(uint32_t row, uint32_t colB) {
    return row * (uint32_t)ROW_B + (colB ^ ((row & 7u) << 4));
}

// ---------------- main kernel ----------------
__global__ void __launch_bounds__(THREADS, 1)
grouped_gemm_hmma(const int* __restrict__ seg_indptr,
                  const int* __restrict__ widx,
                  float* __restrict__ C)
{
    extern __shared__ char smem[];
    const uint32_t sb = (uint32_t)__cvta_generic_to_shared(smem);
    const int tid = threadIdx.x;
    const int wid = tid >> 5;
    const int lane = tid & 31;

    const uint32_t mbF = sb + MBAR_OFF;        // full[i]  at +8*i (3 stages)
    const uint32_t mbE = sb + MBAR_OFF + 24;   // empty[i] at +8*i
    volatile unsigned* sTile = (volatile unsigned*)(smem + MBAR_OFF + 64);
    int* sPref = (int*)(smem + PREF_OFF);      // [0..64] unit prefix (x NCOLS)

    int sv[E_SEG + 1];
    #pragma unroll
    for (int s = 0; s <= E_SEG; ++s) sv[s] = seg_indptr[s];

    if (tid == 0) {
        #pragma unroll
        for (int i = 0; i < NSTAGE; ++i) {
            mbar_init(mbF + i * 8, 128);   // one .noinc arrival per producer thread
            mbar_init(mbE + i * 8, 8);     // one arrival per consumer warp
        }
        int acc = 0;
        sPref[0] = 0;
        for (int m = 0; m < NBANDS; ++m) {
            const int lo = m * BM, hi = lo + BM;
            int c = 0;
            #pragma unroll
            for (int s = 0; s < E_SEG; ++s)
                if (max(sv[s], lo) < min(sv[s + 1], hi)) ++c;
            acc += NCOLS * c;
            sPref[m + 1] = acc;
        }
    }
    __syncthreads();
    const int nUnits = sPref[NBANDS];

    // consumer warp layout (wid 0..7): 64x32 tiles
    const int warp_m = wid >> 2;            // 0..1
    const int warp_n = wid & 3;             // 0..3
    const uint32_t aRow = (uint32_t)(warp_m * 64 + (lane & 15));
    const uint32_t bRow = (uint32_t)(warp_n * 32 + (lane & 7) + ((lane >> 4) & 1) * 8);
    const uint32_t aSel = (uint32_t)((lane >> 4) * 16);
    const uint32_t bSel = (uint32_t)(((lane >> 3) & 1) * 16);
    const int khSkew = (wid & 1) * 4;       // decorrelate LDSM bursts per SMSP

    // producer thread layout (tid 256..383): 2048 chunks/matrix, 16 per thread
    const int pt = tid - 256;

    int pst = 0, pph = 1;   // producer cursor
    int cst = 0, cph = 0;   // consumer cursor

    #pragma unroll 1
    for (;;) {
        __syncthreads();
        if (tid == 0) *sTile = atomicAdd(&g_tileCtr, 1u);
        __syncthreads();
        const unsigned u = *sTile;
        if (u >= (unsigned)nUnits) break;

        // decode unit -> (band, item, col)
        int blo = 0, bhi = NBANDS;
        while (bhi - blo > 1) {
            const int mid = (blo + bhi) >> 1;
            if ((unsigned)sPref[mid] <= u) blo = mid; else bhi = mid;
        }
        const int band = blo;
        const int rem = (int)u - sPref[band];
        const int it = rem >> 3;               // item within band
        const int col = rem & 7;               // column tile
        const int row0 = band * BM;
        const int col0 = col * BN;

        // find it-th intersecting segment of this band
        int rloI = 0, rhiI = 0;
        const __half* __restrict__ be = g_Bh;
        {
            int cnt = 0;
            #pragma unroll
            for (int s = 0; s < E_SEG; ++s) {
                const int rl = max(sv[s], row0);
                const int rh = min(sv[s + 1], row0 + BM);
                if (rl < rh) {
                    if (cnt == it) {
                        rloI = rl; rhiI = rh;
                        be = g_Bh + (size_t)widx[s] * ((size_t)N_DIM * K_DIM);
                    }
                    ++cnt;
                }
            }
        }

        if (wid >= 8) {
            // ================= PRODUCER WARPS (128 threads) =================
            #pragma unroll 1
            for (int kt = 0; kt < KT; ++kt) {
                mbar_wait(mbE + pst * 8, (uint32_t)pph);
                const uint32_t stg = sb + pst * STAGE_BYTES;
                const int keB = kt * BK;
                // each matrix: 128 rows x 16 chunks = 2048 chunks; 16/thread
                #pragma unroll
                for (int blk = 0; blk < 16; ++blk) {
                    const int id = blk * 128 + pt;
                    const uint32_t r = (uint32_t)(id >> 4);
                    const int c = id & 15;
                    const uint32_t so = swz(r, (uint32_t)(c * 16));
                    cp16(stg + so,
                         g_Ah + (size_t)(row0 + (int)r) * K_DIM + keB + c * 8);
                    cp16(stg + MAT_BYTES + so,
                         be + (size_t)(col0 + (int)r) * K_DIM + keB + c * 8);
                }
                cpasync_arrive(mbF + pst * 8);
                if (++pst == NSTAGE) { pst = 0; pph ^= 1; }
            }
        } else {
            // ================= CONSUMER WARPS =================
            const int wr0 = row0 + warp_m * 64;
            const bool active = (rhiI > wr0) && (rloI < wr0 + 64);

            if (!active) {
                #pragma unroll 1
                for (int kt = 0; kt < KT; ++kt) {
                    mbar_wait(mbF + cst * 8, (uint32_t)cph);
                    if (lane == 0) mbar_arrive(mbE + cst * 8);
                    if (++cst == NSTAGE) { cst = 0; cph ^= 1; }
                }
            } else {
                float acc[4][4][4];
                #pragma unroll
                for (int i = 0; i < 4; ++i)
                    #pragma unroll
                    for (int j = 0; j < 4; ++j)
                        #pragma unroll
                        for (int p = 0; p < 4; ++p) acc[i][j][p] = 0.f;

                #pragma unroll 1
                for (int kt = 0; kt < KT; ++kt) {
                    mbar_wait(mbF + cst * 8, (uint32_t)cph);

                    const uint32_t stg   = sb + cst * STAGE_BYTES;
                    const uint32_t stgAh = stg;
                    const uint32_t stgBh = stg + MAT_BYTES;

                    #pragma unroll
                    for (int khi = 0; khi < 8; khi += 2) {
                        const int kh0 = (khi + khSkew) & 7;
                        const int kh1 = (khi + 1 + khSkew) & 7;
                        const uint32_t aCB0 = (uint32_t)(kh0 * 32) + aSel;
                        const uint32_t bCB0 = (uint32_t)(kh0 * 32) + bSel;
                        const uint32_t aCB1 = (uint32_t)(kh1 * 32) + aSel;
                        const uint32_t bCB1 = (uint32_t)(kh1 * 32) + bSel;

                        // load both kh fragments up front -> long MMA run
                        uint32_t a0[4][4], b0[2][4], a1[4][4], b1[2][4];
                        #pragma unroll
                        for (int mt = 0; mt < 4; ++mt)
                            ldsm4(stgAh + swz(aRow + mt * 16, aCB0), a0[mt]);
                        #pragma unroll
                        for (int p = 0; p < 2; ++p)
                            ldsm4(stgBh + swz(bRow + p * 16, bCB0), b0[p]);
                        #pragma unroll
                        for (int mt = 0; mt < 4; ++mt)
                            ldsm4(stgAh + swz(aRow + mt * 16, aCB1), a1[mt]);
                        #pragma unroll
                        for (int p = 0; p < 2; ++p)
                            ldsm4(stgBh + swz(bRow + p * 16, bCB1), b1[p]);

                        #pragma unroll
                        for (int mt = 0; mt < 4; ++mt)
                            #pragma unroll
                            for (int nt = 0; nt < 4; ++nt)
                                mma16816(acc[mt][nt], a0[mt],
                                         b0[nt >> 1][(nt & 1) * 2],
                                         b0[nt >> 1][(nt & 1) * 2 + 1]);
                        #pragma unroll
                        for (int mt = 0; mt < 4; ++mt)
                            #pragma unroll
                            for (int nt = 0; nt < 4; ++nt)
                                mma16816(acc[mt][nt], a1[mt],
                                         b1[nt >> 1][(nt & 1) * 2],
                                         b1[nt >> 1][(nt & 1) * 2 + 1]);
                    }

                    if (lane == 0) mbar_arrive(mbE + cst * 8);
                    if (++cst == NSTAGE) { cst = 0; cph ^= 1; }
                }

                // epilogue: masked rows for this unit's segment
                const int cbase = col0 + warp_n * 32 + (lane & 3) * 2;
                #pragma unroll
                for (int mt = 0; mt < 4; ++mt) {
                    const int r0 = wr0 + mt * 16 + (lane >> 2);
                    const int r1 = r0 + 8;
                    const bool w0 = (r0 >= rloI && r0 < rhiI);
                    const bool w1 = (r1 >= rloI && r1 < rhiI);
                    #pragma unroll
                    for (int nt = 0; nt < 4; ++nt) {
                        const int cc = cbase + nt * 8;
                        if (w0) *(float2*)&C[(size_t)r0 * N_DIM + cc] =
                                    make_float2(acc[mt][nt][0], acc[mt][nt][1]);
                        if (w1) *(float2*)&C[(size_t)r1 * N_DIM + cc] =
                                    make_float2(acc[mt][nt][2], acc[mt][nt][3]);
                    }
                }
            }
        }
    }
}

extern "C" void kernel_launch(void* const* d_in, const int* in_sizes, int n_in,
                              void* d_out, int out_size)
{
    const float* a = (const float*)d_in[0];    // [M, K]
    const float* b = (const float*)d_in[1];    // [E, N, K]
    const int* seg = nullptr;
    const int* widx = nullptr;
    for (int i = 0; i < n_in; ++i) {
        if (in_sizes[i] == E_SEG + 1)  seg  = (const int*)d_in[i];
        else if (in_sizes[i] == E_SEG) widx = (const int*)d_in[i];
    }
    float* c = (float*)d_out;

    split_AB<<<(NA4 + NB4) / 512, 256>>>((const float4*)a, (const float4*)b);

    cudaFuncSetAttribute(grouped_gemm_hmma,
                         cudaFuncAttributeMaxDynamicSharedMemorySize, SMEM_TOTAL);
    grouped_gemm_hmma<<<GRID_P, THREADS, SMEM_TOTAL>>>(seg, widx, c);
}